// round 8
// baseline (speedup 1.0000x reference)
#include <cuda_runtime.h>
#include <cuda_bf16.h>
#include <cstdint>

// PrRoIPool2D, separable two-pass, per-bin 4-tap y-pass.
// Fixed shapes: features [2, 256, 50, 50] f32, rois [256, 5], out [256,256,7,7] f32.
//
// Block = (roi, 32-channel group), 256 threads, 6 blocks/SM.
//  0) All threads derive window bounds from the roi (broadcast LDGs).
//  1) Parallel weight setup, ONE barrier: warp0 -> 4-tap x table + offsets,
//     warp1 -> 4-tap y table (1/area folded) + absolute row offsets.
//  2) y-pass: thread=(x, ch pair). Per bin p: 8 unpredicated LDG (uniform row
//     offset) + 2 independent dot4 -> ytmp[p][ch][x] (pitch 17, conflict-free).
//  3) x-pass: warp=p, lane=ch -> s_out (stride 49, conflict-free).
//  4) float4 coalesced writeback.

#define PH 7
#define PW 7
#define KW 4
#define CG 32
#define SCALE 0.0625f
#define YPITCH 17

#define C_   256
#define H_   50
#define W_   50
#define HW_  (H_ * W_)
#define CHW_ (C_ * HW_)

__device__ __forceinline__ float hat_cdf(float t) {
    t = fminf(fmaxf(t, -1.0f), 1.0f);
    return (t < 0.0f) ? 0.5f * (t + 1.0f) * (t + 1.0f)
                      : 0.5f + t - 0.5f * t * t;
}

__global__ void __launch_bounds__(256, 6)
prroi_pool_kernel(const float* __restrict__ feat,
                  const float* __restrict__ rois,
                  float* __restrict__ out)
{
    const int r  = blockIdx.x >> 3;
    const int cg = blockIdx.x & 7;

    __shared__ __align__(16) float s_ytmp[PH * CG * YPITCH];   // 15.2 KB
    __shared__ __align__(16) float s_out[CG * PH * PW];        // 6.3 KB
    __shared__ __align__(16) float s_wy[PH][KW];               // 1/area folded
    __shared__ __align__(16) float s_wx[PW][KW];
    __shared__ int s_offy[PH];          // y0[p] * W_   (absolute row word offset)
    __shared__ int s_offx[PW];          // x0[q] - wstart

    const int tid = threadIdx.x;

    // ---- 0: window bounds, derived uniformly per thread ----
    const float* roi = rois + r * 5;
    const float b0 = roi[0];
    const float x1 = roi[1] * SCALE;
    const float y1 = roi[2] * SCALE;
    const float x2 = roi[3] * SCALE;
    const float y2 = roi[4] * SCALE;
    const float bw = (x2 - x1) * (1.0f / PW);
    const float bh = (y2 - y1) * (1.0f / PH);

    const int wstart = min(max((int)ceilf(x1 - 1.0f), 0), W_ - KW);
    const int wend   = min(max((int)ceilf(x1 + 6.0f * bw - 1.0f), 0), W_ - KW);
    const int ww     = wend + KW - wstart;                    // <= 15 (block-uniform)
    const int base   = (int)b0 * CHW_ + cg * (CG * HW_);

    const float area = bw * bh;
    const float inva = (area > 0.0f) ? (1.0f / area) : 0.0f;

    // ---- 1: parallel weight setup (one barrier) ----
    if (tid < PW * KW) {                          // warp0: x table
        const int q = tid >> 2;
        const int k = tid & 3;
        const float lo = x1 + (float)q * bw;
        const float hi = lo + bw;
        const int i0 = min(max((int)ceilf(lo - 1.0f), 0), W_ - KW);
        s_wx[q][k] = hat_cdf(hi - (float)(i0 + k)) - hat_cdf(lo - (float)(i0 + k));
        if (k == 0) s_offx[q] = i0 - wstart;
    } else if (tid >= 32 && tid < 32 + PH * KW) { // warp1: y table (scaled)
        const int z = tid - 32;
        const int p = z >> 2;
        const int k = z & 3;
        const float lo = y1 + (float)p * bh;
        const float hi = lo + bh;
        const int i0 = min(max((int)ceilf(lo - 1.0f), 0), H_ - KW);
        s_wy[p][k] = (hat_cdf(hi - (float)(i0 + k)) - hat_cdf(lo - (float)(i0 + k))) * inva;
        if (k == 0) s_offy[p] = i0 * W_;
    }
    __syncthreads();

    // ---- 2: y-pass: thread = (x, channel pair); per-bin 4-tap dots ----
    const int lane = tid & 31;
    {
        const int warp = tid >> 5;
        const int x    = lane & 15;                    // 0..15
        const int ch0  = warp * 2 + (lane >> 4);       // 0..15 ; +16 partner
        const bool xin = (x < ww);
        const int  xc  = min(x, ww - 1);               // clamp: no OOB, garbage unsaved

        const float* gA = feat + base + ch0 * HW_ + wstart + xc;
        const float* gB = gA + 16 * HW_;

        float accA[PH], accB[PH];
        #pragma unroll
        for (int p = 0; p < PH; p++) {
            const int oy = s_offy[p];                  // uniform
            const float4 wy = *reinterpret_cast<const float4*>(s_wy[p]);
            const float* a = gA + oy;
            const float* b = gB + oy;
            // 8 independent LDGs (imm row offsets), two dot4 chains
            const float a0 = a[0], a1 = a[W_], a2 = a[2 * W_], a3 = a[3 * W_];
            const float b0v = b[0], b1v = b[W_], b2v = b[2 * W_], b3v = b[3 * W_];
            float sA = a0 * wy.x;
            float sB = b0v * wy.x;
            sA = fmaf(a1, wy.y, sA);  sB = fmaf(b1v, wy.y, sB);
            sA = fmaf(a2, wy.z, sA);  sB = fmaf(b2v, wy.z, sB);
            sA = fmaf(a3, wy.w, sA);  sB = fmaf(b3v, wy.w, sB);
            accA[p] = sA;
            accB[p] = sB;
        }

        if (xin) {
            #pragma unroll
            for (int p = 0; p < PH; p++) {
                s_ytmp[(p * CG + ch0)      * YPITCH + x] = accA[p];
                s_ytmp[(p * CG + ch0 + 16) * YPITCH + x] = accB[p];
            }
        }
    }
    __syncthreads();

    // ---- 3: x-pass: warp = p, lane = ch ----
    {
        const int wp = tid >> 5;
        if (wp < PH) {
            const float* yt = s_ytmp + (wp * CG + lane) * YPITCH;
            float* so = s_out + lane * (PH * PW) + wp * PW;
            #pragma unroll
            for (int q = 0; q < PW; q++) {
                const int xo = s_offx[q];
                const float4 wx = *reinterpret_cast<const float4*>(s_wx[q]);
                float v = yt[xo] * wx.x;
                v = fmaf(yt[xo + 1], wx.y, v);
                v = fmaf(yt[xo + 2], wx.z, v);
                v = fmaf(yt[xo + 3], wx.w, v);
                so[q] = v;                             // lane stride 49: conflict-free
            }
        }
    }
    __syncthreads();

    // ---- 4: float4 coalesced writeback ----
    {
        float4* o4 = reinterpret_cast<float4*>(out + r * (C_ * PH * PW) + cg * (CG * PH * PW));
        const float4* s4 = reinterpret_cast<const float4*>(s_out);
        #pragma unroll
        for (int i = tid; i < (CG * PH * PW) / 4; i += 256)   // 392 float4s
            o4[i] = s4[i];
    }
}

extern "C" void kernel_launch(void* const* d_in, const int* in_sizes, int n_in,
                              void* d_out, int out_size)
{
    const float* feat = (const float*)d_in[0];
    const float* rois = (const float*)d_in[1];
    float* out = (float*)d_out;

    const int R = in_sizes[1] / 5;       // 256
    prroi_pool_kernel<<<R * (C_ / CG), 256>>>(feat, rois, out);
}